// round 9
// baseline (speedup 1.0000x reference)
#include <cuda_runtime.h>
#include <cstdint>

#define TOTALW 4096L

__constant__ int c_layer[32] = {0,1,2,2,2,3,3,3,4,4,4,4,4,5,5,5,5,5,6,6,6,6,6,6,6,7,7,7,7,7,7,7};
__constant__ int c_ntile[32] = {0,0,0,1,2,0,1,2,0,1,2,3,4,0,1,2,3,4,0,1,2,3,4,5,6,0,1,2,3,4,5,6};
__constant__ int c_start[8]  = {0,128,256,640,1024,1664,2304,3200};
__constant__ int c_nb[8]     = {1,1,3,3,5,5,7,7};

struct KParams { const float* x; const float* W[8]; float* out; };

__device__ __forceinline__ uint32_t smem_u32(const void* p) {
    uint32_t a;
    asm("{ .reg .u64 t; cvta.to.shared.u64 t, %1; cvt.u32.u64 %0, t; }" : "=r"(a) : "l"(p));
    return a;
}
__device__ __forceinline__ uint32_t sw128(uint32_t o) { return o ^ ((o >> 3) & 0x70); }
__device__ __forceinline__ float tf32r(float f) {
    uint32_t o; asm("cvt.rna.tf32.f32 %0, %1;" : "=r"(o) : "f"(f));
    return __uint_as_float(o);
}
__device__ __forceinline__ void ldsm4(uint32_t r[4], uint32_t a) {
    asm volatile("ldmatrix.sync.aligned.m8n8.x4.shared.b16 {%0,%1,%2,%3}, [%4];"
                 : "=r"(r[0]), "=r"(r[1]), "=r"(r[2]), "=r"(r[3]) : "r"(a));
}
__device__ __forceinline__ void mma8(float* c, const uint32_t* a, uint32_t b0, uint32_t b1) {
    asm volatile("mma.sync.aligned.m16n8k8.row.col.f32.tf32.tf32.f32 "
                 "{%0,%1,%2,%3},{%4,%5,%6,%7},{%8,%9},{%0,%1,%2,%3};"
                 : "+f"(c[0]), "+f"(c[1]), "+f"(c[2]), "+f"(c[3])
                 : "r"(a[0]), "r"(a[1]), "r"(a[2]), "r"(a[3]), "r"(b0), "r"(b1));
}

__global__ void __launch_bounds__(256) ielin_kernel(KParams p) {
    extern __shared__ char smem[];                 // [2][ A 16KB | B 16KB ]
    const uint32_t sb = smem_u32(smem);
    const int tid = threadIdx.x, lane = tid & 31, wid = tid >> 5;
    const int warpM = wid >> 2, warpN = wid & 3;   // 2 x 4 warps, warp tile 64x32

    const int bid   = blockIdx.x;
    const int mt    = bid >> 5;                    // 256 m-tiles of 128 rows
    const int t     = bid & 31;
    const int layer = c_layer[t], ntile = c_ntile[t];
    const int w     = c_nb[layer] * 128;
    const int start = c_start[layer];
    const int nk    = c_nb[layer] * 4;             // K chunks of 32
    const long row0 = (long)mt * 128;
    const int ncol0 = ntile * 128;

    // ---- gmem staging geometry: 1024 16B chunks per tile, 4 per thread ----
    const float* xg = p.x + row0 * TOTALW + start + (long)(tid >> 3) * TOTALW + (tid & 7) * 4;
    const float* wg = p.W[layer] + (long)ncol0 * w + (long)(tid >> 3) * w + (tid & 7) * 4;
    uint32_t stsOff[4];
    #pragma unroll
    for (int i = 0; i < 4; i++) stsOff[i] = sw128((uint32_t)(tid + i * 256) << 4);

    float4 stA[4], stB[4];
    auto ldg = [&](int kc) {
        const float* xa = xg + kc * 32;
        const float* wa = wg + kc * 32;
        #pragma unroll
        for (int i = 0; i < 4; i++) {
            stA[i] = *reinterpret_cast<const float4*>(xa + (long)i * 32 * TOTALW);
            stB[i] = *reinterpret_cast<const float4*>(wa + (long)i * 32 * w);
        }
    };
    auto sts = [&](int buf) {
        char* base = smem + buf * 32768;
        #pragma unroll
        for (int i = 0; i < 4; i++) {
            float4 a = stA[i];
            a.x = tf32r(a.x); a.y = tf32r(a.y); a.z = tf32r(a.z); a.w = tf32r(a.w);
            *reinterpret_cast<float4*>(base + stsOff[i]) = a;
            float4 b = stB[i];
            b.x = tf32r(b.x); b.y = tf32r(b.y); b.z = tf32r(b.z); b.w = tf32r(b.w);
            *reinterpret_cast<float4*>(base + 16384 + stsOff[i]) = b;
        }
    };

    float acc[4][4][4] = {};

    // ---- ldmatrix lane geometry ----
    const int ml = lane >> 3, lr = lane & 7;
    const uint32_t aRowBase   = (uint32_t)(warpM * 64 + (ml & 1) * 8 + lr);  // + mi*16
    const uint32_t bRowBase   = (uint32_t)(warpN * 32 + lr);                 // + ni*8
    const uint32_t aChunkHalf = (uint32_t)(ml >> 1);                         // + ks*2

    auto compute = [&](int buf) {
        const uint32_t Ab = sb + buf * 32768;
        const uint32_t Bb = Ab + 16384;
        uint32_t bfr[4][4];
        #pragma unroll
        for (int ks = 0; ks < 4; ks++) {
            if (!(ks & 1)) {                      // B frags for kstep pair (ks, ks+1)
                #pragma unroll
                for (int ni = 0; ni < 4; ni++) {
                    uint32_t off = (bRowBase + ni * 8) * 128 + ((ks << 1) + ml) * 16;
                    ldsm4(bfr[ni], Bb + sw128(off));
                }
            }
            uint32_t afr[4][4];
            #pragma unroll
            for (int mi = 0; mi < 4; mi++) {
                uint32_t off = (aRowBase + mi * 16) * 128 + (ks * 2 + aChunkHalf) * 16;
                ldsm4(afr[mi], Ab + sw128(off));
            }
            #pragma unroll
            for (int mi = 0; mi < 4; mi++)
                #pragma unroll
                for (int ni = 0; ni < 4; ni++)
                    mma8(acc[mi][ni], afr[mi], bfr[ni][(ks & 1) * 2], bfr[ni][(ks & 1) * 2 + 1]);
        }
    };

    // ---- pipelined mainloop ----
    ldg(0); sts(0); __syncthreads();
    for (int kc = 0; kc < nk; kc++) {
        if (kc + 1 < nk) ldg(kc + 1);
        compute(kc & 1);
        if (kc + 1 < nk) sts((kc + 1) & 1);
        __syncthreads();
    }

    // ---- epilogue: direct stores (32B-sector aligned float2s) ----
    const int r0l = lane >> 2, c0l = (lane & 3) * 2;
    float* ob = p.out + (row0 + warpM * 64 + r0l) * TOTALW + start + ncol0 + warpN * 32 + c0l;
    #pragma unroll
    for (int mi = 0; mi < 4; mi++)
        #pragma unroll
        for (int ni = 0; ni < 4; ni++) {
            float* o0 = ob + (long)mi * 16 * TOTALW + ni * 8;
            *reinterpret_cast<float2*>(o0) = make_float2(acc[mi][ni][0], acc[mi][ni][1]);
            *reinterpret_cast<float2*>(o0 + 8 * TOTALW) = make_float2(acc[mi][ni][2], acc[mi][ni][3]);
        }
}

extern "C" void kernel_launch(void* const* d_in, const int* in_sizes, int n_in,
                              void* d_out, int out_size) {
    KParams p;
    p.x = (const float*)d_in[0];
    for (int i = 0; i < 8; i++) p.W[i] = (const float*)d_in[1 + i];
    p.out = (float*)d_out;
    cudaFuncSetAttribute(ielin_kernel, cudaFuncAttributeMaxDynamicSharedMemorySize, 65536);
    ielin_kernel<<<8192, 256, 65536>>>(p);
}

// round 11
// speedup vs baseline: 1.6260x; 1.6260x over previous
#include <cuda_runtime.h>
#include <cstdint>

#define TOTALW 4096L
#define S 3                         // cp.async pipeline stages
#define STG 32768                   // bytes per stage: A 16KB + B 16KB

__constant__ int c_layer[32] = {0,1,2,2,2,3,3,3,4,4,4,4,4,5,5,5,5,5,6,6,6,6,6,6,6,7,7,7,7,7,7,7};
__constant__ int c_ntile[32] = {0,0,0,1,2,0,1,2,0,1,2,3,4,0,1,2,3,4,0,1,2,3,4,5,6,0,1,2,3,4,5,6};
__constant__ int c_start[8]  = {0,128,256,640,1024,1664,2304,3200};
__constant__ int c_nb[8]     = {1,1,3,3,5,5,7,7};
__constant__ long c_wroff[8] = {0,16384,32768,180224,327680,737280,1146880,1949696};

__device__ float g_Wr[2752512];     // 10.5 MB: all 8 W pre-rounded to tf32 (rna)

struct KParams { const float* x; const float* W[8]; float* out; };

__device__ __forceinline__ uint32_t smem_u32(const void* p) {
    uint32_t a;
    asm("{ .reg .u64 t; cvta.to.shared.u64 t, %1; cvt.u32.u64 %0, t; }" : "=r"(a) : "l"(p));
    return a;
}
__device__ __forceinline__ uint32_t sw128(uint32_t o) { return o ^ ((o >> 3) & 0x70); }
__device__ __forceinline__ float tf32r(float f) {
    uint32_t o; asm("cvt.rna.tf32.f32 %0, %1;" : "=r"(o) : "f"(f));
    return __uint_as_float(o);
}
__device__ __forceinline__ void cpa16(uint32_t d, const void* s) {
    asm volatile("cp.async.cg.shared.global [%0], [%1], 16;" :: "r"(d), "l"(s));
}
#define CP_COMMIT() asm volatile("cp.async.commit_group;" ::: "memory")
#define CP_WAIT1()  asm volatile("cp.async.wait_group 1;" ::: "memory")

__device__ __forceinline__ void ldsm4(uint32_t r[4], uint32_t a) {
    asm volatile("ldmatrix.sync.aligned.m8n8.x4.shared.b16 {%0,%1,%2,%3}, [%4];"
                 : "=r"(r[0]), "=r"(r[1]), "=r"(r[2]), "=r"(r[3]) : "r"(a));
}
__device__ __forceinline__ void mma8(float* c, const uint32_t* a, uint32_t b0, uint32_t b1) {
    asm volatile("mma.sync.aligned.m16n8k8.row.col.f32.tf32.tf32.f32 "
                 "{%0,%1,%2,%3},{%4,%5,%6,%7},{%8,%9},{%0,%1,%2,%3};"
                 : "+f"(c[0]), "+f"(c[1]), "+f"(c[2]), "+f"(c[3])
                 : "r"(a[0]), "r"(a[1]), "r"(a[2]), "r"(a[3]), "r"(b0), "r"(b1));
}

// pre-pass: round all W into g_Wr with rna (removes half the tf32 truncation bias)
__global__ void __launch_bounds__(256) round_w_kernel(KParams p) {
    const int l = blockIdx.y;
    const long n = (long)c_nb[l] * 128 * (long)c_nb[l] * 128;
    const float* __restrict__ src = p.W[l];
    float* __restrict__ dst = g_Wr + c_wroff[l];
    for (long i = (long)blockIdx.x * blockDim.x + threadIdx.x; i < n;
         i += (long)gridDim.x * blockDim.x)
        dst[i] = tf32r(src[i]);
}

__global__ void __launch_bounds__(256, 2) ielin_kernel(KParams p) {
    extern __shared__ char smem[];                 // [3][ A 16KB | B 16KB ]
    const uint32_t sb = smem_u32(smem);
    const int tid = threadIdx.x, lane = tid & 31, wid = tid >> 5;
    const int warpM = wid >> 2, warpN = wid & 3;   // 2 x 4 warps, warp tile 64x32

    const int bid   = blockIdx.x;
    const int mt    = bid >> 5;                    // 256 m-tiles of 128 rows
    const int t     = bid & 31;
    const int layer = c_layer[t], ntile = c_ntile[t];
    const int w     = c_nb[layer] * 128;
    const int start = c_start[layer];
    const int nk    = c_nb[layer] * 4;             // K chunks of 32  (nk >= 4 >= S-1)
    const long row0 = (long)mt * 128;
    const int ncol0 = ntile * 128;

    // ---- per-thread cp.async geometry: 1024 16B units per 16KB tile, 4/thread ----
    const float* xg = p.x + row0 * TOTALW + start + (long)(tid >> 3) * TOTALW + (tid & 7) * 4;
    const float* wg = g_Wr + c_wroff[layer] + (long)ncol0 * w + (long)(tid >> 3) * w + (tid & 7) * 4;
    uint32_t dOff[4];
    #pragma unroll
    for (int i = 0; i < 4; i++) dOff[i] = sw128((uint32_t)(tid + i * 256) << 4);

    auto issue = [&](int kc, int st) {
        const float* xa = xg + kc * 32;
        const float* wa = wg + kc * 32;
        const uint32_t base = sb + st * STG;
        #pragma unroll
        for (int i = 0; i < 4; i++)
            cpa16(base + dOff[i], xa + (long)i * 32 * TOTALW);
        #pragma unroll
        for (int i = 0; i < 4; i++)
            cpa16(base + 16384 + dOff[i], wa + (long)i * 32 * w);
    };

    float acc[4][4][4] = {};

    // ---- ldmatrix lane geometry ----
    const int ml = lane >> 3, lr = lane & 7;
    const uint32_t aRowBase   = (uint32_t)(warpM * 64 + (ml & 1) * 8 + lr);  // + mi*16
    const uint32_t bRowBase   = (uint32_t)(warpN * 32 + lr);                 // + ni*8
    const uint32_t aChunkHalf = (uint32_t)(ml >> 1);                         // + ks*2

    auto compute = [&](int st) {
        const uint32_t Ab = sb + st * STG;
        const uint32_t Bb = Ab + 16384;
        uint32_t bfr[4][4];
        #pragma unroll
        for (int ks = 0; ks < 4; ks++) {
            if (!(ks & 1)) {                      // B frags for kstep pair (ks, ks+1)
                #pragma unroll
                for (int ni = 0; ni < 4; ni++) {
                    uint32_t off = (bRowBase + ni * 8) * 128 + ((ks << 1) + ml) * 16;
                    ldsm4(bfr[ni], Bb + sw128(off));
                }
            }
            uint32_t afr[4][4];
            #pragma unroll
            for (int mi = 0; mi < 4; mi++) {
                uint32_t off = (aRowBase + mi * 16) * 128 + (ks * 2 + aChunkHalf) * 16;
                ldsm4(afr[mi], Ab + sw128(off));
            }
            #pragma unroll
            for (int mi = 0; mi < 4; mi++)
                #pragma unroll
                for (int ni = 0; ni < 4; ni++)
                    mma8(acc[mi][ni], afr[mi], bfr[ni][(ks & 1) * 2], bfr[ni][(ks & 1) * 2 + 1]);
        }
    };

    // ---- 3-stage cp.async pipeline ----
    issue(0, 0); CP_COMMIT();
    issue(1, 1); CP_COMMIT();
    int stC = 0, stW = 2;                          // compute stage / write stage
    for (int kc = 0; kc < nk; kc++) {
        CP_WAIT1();                                // chunk kc landed (this thread)
        __syncthreads();                           // all threads' copies visible; stage stW retired
        if (kc + S - 1 < nk) issue(kc + S - 1, stW);
        CP_COMMIT();                               // keep group count uniform
        compute(stC);
        stC = (stC == S - 1) ? 0 : stC + 1;
        stW = (stW == S - 1) ? 0 : stW + 1;
    }

    // ---- epilogue: direct stores (32B-sector aligned float2s) ----
    const int r0l = lane >> 2, c0l = (lane & 3) * 2;
    float* ob = p.out + (row0 + warpM * 64 + r0l) * TOTALW + start + ncol0 + warpN * 32 + c0l;
    #pragma unroll
    for (int mi = 0; mi < 4; mi++)
        #pragma unroll
        for (int ni = 0; ni < 4; ni++) {
            float* o0 = ob + (long)mi * 16 * TOTALW + ni * 8;
            *reinterpret_cast<float2*>(o0) = make_float2(acc[mi][ni][0], acc[mi][ni][1]);
            *reinterpret_cast<float2*>(o0 + 8 * TOTALW) = make_float2(acc[mi][ni][2], acc[mi][ni][3]);
        }
}

extern "C" void kernel_launch(void* const* d_in, const int* in_sizes, int n_in,
                              void* d_out, int out_size) {
    KParams p;
    p.x = (const float*)d_in[0];
    for (int i = 0; i < 8; i++) p.W[i] = (const float*)d_in[1 + i];
    p.out = (float*)d_out;
    round_w_kernel<<<dim3(512, 8), 256>>>(p);
    cudaFuncSetAttribute(ielin_kernel, cudaFuncAttributeMaxDynamicSharedMemorySize, S * STG);
    ielin_kernel<<<8192, 256, S * STG>>>(p);
}